// round 1
// baseline (speedup 1.0000x reference)
#include <cuda_runtime.h>

#define EPSF 1e-20f

// ---------------------------------------------------------------------------
// Scratch pool (static __device__ memory — no allocations allowed).
// Layout (floats):
//   P0x,P0c,P1x,P1c,X1,C1 : 6 x N512   (full-res ping-pong + encoder skip)
//   X2,C2                 : 2 x N256   (skip @256)
//   X3,C3                 : 2 x N128   (skip @128)
//   S0x,S0c,S1x,S1c       : 4 x N256   (small scratch, reused at 256/128/64)
//   WS                    : 256        (per-layer 1/sum(w) tables)
// ---------------------------------------------------------------------------
static constexpr long N512 = 2L * 32 * 512 * 512;   // 16,777,216
static constexpr long N256 = 2L * 32 * 256 * 256;   //  4,194,304
static constexpr long N128 = 2L * 32 * 128 * 128;   //  1,048,576
static constexpr long POOL_FLOATS = 6 * N512 + 2 * N256 + 2 * N128 + 4 * N256 + 256;

__device__ float g_pool[POOL_FLOATS];

// ---------------------------------------------------------------------------
// Packed f32x2 helpers (sm_100+ packed fp32 pipe: doubles FFMA throughput)
// ---------------------------------------------------------------------------
__device__ __forceinline__ unsigned long long pack2(float a, float b) {
    unsigned long long r;
    asm("mov.b64 %0, {%1, %2};" : "=l"(r) : "f"(a), "f"(b));
    return r;
}
__device__ __forceinline__ void unpack2(unsigned long long v, float& a, float& b) {
    asm("mov.b64 {%0, %1}, %2;" : "=f"(a), "=f"(b) : "l"(v));
}
__device__ __forceinline__ void ffma2(unsigned long long& acc, unsigned long long w2,
                                      unsigned long long m2) {
    asm("fma.rn.f32x2 %0, %1, %2, %0;" : "+l"(acc) : "l"(w2), "l"(m2));
}

// ---------------------------------------------------------------------------
// Per-layer 1/sum(w) precompute: inv[l*32+co] = 1 / sum(w_l[co,:,:,:])
// ---------------------------------------------------------------------------
__global__ void wsum_kernel(const float* __restrict__ w1, const float* __restrict__ w2,
                            const float* __restrict__ w3, const float* __restrict__ w4,
                            const float* __restrict__ w5, const float* __restrict__ w6,
                            const float* __restrict__ w7, float* __restrict__ inv) {
    int l = blockIdx.x, co = threadIdx.x;
    const float* w; int n; int nco = 32;
    if      (l == 0) { w = w1; n = 1 * 25; }
    else if (l == 1) { w = w2; n = 32 * 25; }
    else if (l == 2) { w = w3; n = 32 * 25; }
    else if (l == 3) { w = w4; n = 64 * 9; }
    else if (l == 4) { w = w5; n = 64 * 9; }
    else if (l == 5) { w = w6; n = 64 * 9; }
    else             { w = w7; n = 32;  nco = 1; }
    if (co >= nco) return;
    float s = 0.f;
    for (int i = 0; i < n; i++) s += w[co * n + i];
    inv[l * 32 + co] = 1.0f / s;
}

// ---------------------------------------------------------------------------
// Generic normalized conv, KSxKS, CIN -> 32, same-padding.
// Block: 256 threads = 16x16 spatial tile; each thread holds all 32 output
// channels as 16 packed (even,odd) f32x2 accumulators for nomin and denom.
// Weights staged per-ci-chunk in smem, transposed to [kk][co] for LDS.128.
// ---------------------------------------------------------------------------
template <int CIN, int KS, int HH, int WW>
__global__ __launch_bounds__(256)
void nconv_kernel(const float* __restrict__ xin, const float* __restrict__ cin,
                  long bstride, long cstride,
                  const float* __restrict__ w, const float* __restrict__ bias,
                  const float* __restrict__ winv,
                  float* __restrict__ xout, float* __restrict__ cout) {
    constexpr int PAD = KS / 2;
    constexpr int KK = KS * KS;
    constexpr int CHUNK = (CIN >= 8) ? 8 : CIN;
    __shared__ __align__(16) float ws[CHUNK * KK][32];

    const int tx = threadIdx.x & 15, ty = threadIdx.x >> 4;
    const int x = (blockIdx.x << 4) + tx;
    const int y = (blockIdx.y << 4) + ty;
    const int b = blockIdx.z;

    unsigned long long accN[16], accD[16];
#pragma unroll
    for (int i = 0; i < 16; i++) { accN[i] = 0ULL; accD[i] = 0ULL; }

    bool vy[KS], vx[KS];
#pragma unroll
    for (int k = 0; k < KS; k++) {
        vy[k] = (unsigned)(y + k - PAD) < (unsigned)HH;
        vx[k] = (unsigned)(x + k - PAD) < (unsigned)WW;
    }

    const long pix = (long)y * WW + x;

    for (int ci0 = 0; ci0 < CIN; ci0 += CHUNK) {
        for (int i = threadIdx.x; i < CHUNK * KK * 32; i += 256)
            ws[i >> 5][i & 31] = w[((long)(i & 31) * CIN + ci0) * KK + (i >> 5)];
        __syncthreads();

#pragma unroll 1
        for (int cil = 0; cil < CHUNK; cil++) {
            const float* xp = xin + (long)b * bstride + (long)(ci0 + cil) * cstride + pix;
            const float* cp = cin + (long)b * bstride + (long)(ci0 + cil) * cstride + pix;
#pragma unroll
            for (int ky = 0; ky < KS; ky++) {
#pragma unroll
                for (int kx = 0; kx < KS; kx++) {
                    const int off = (ky - PAD) * WW + (kx - PAD);
                    const bool v = vy[ky] && vx[kx];
                    float cv = v ? __ldg(cp + off) : 0.f;
                    float xv = v ? __ldg(xp + off) : 0.f;
                    float xc = xv * cv;
                    unsigned long long xc2 = pack2(xc, xc);
                    unsigned long long cv2 = pack2(cv, cv);
                    const int kk = cil * KK + ky * KS + kx;
#pragma unroll
                    for (int q = 0; q < 8; q++) {
                        ulonglong2 wv = *reinterpret_cast<const ulonglong2*>(&ws[kk][q * 4]);
                        ffma2(accN[2 * q],     wv.x, xc2);
                        ffma2(accD[2 * q],     wv.x, cv2);
                        ffma2(accN[2 * q + 1], wv.y, xc2);
                        ffma2(accD[2 * q + 1], wv.y, cv2);
                    }
                }
            }
        }
        __syncthreads();
    }

    constexpr long PLANE = (long)HH * WW;
#pragma unroll
    for (int q = 0; q < 16; q++) {
        float n0, n1, d0, d1;
        unpack2(accN[q], n0, n1);
        unpack2(accD[q], d0, d1);
        const int co0 = 2 * q, co1 = 2 * q + 1;
        const long o0 = ((long)b * 32 + co0) * PLANE + pix;
        const long o1 = o0 + PLANE;
        xout[o0] = n0 / (d0 + EPSF) + bias[co0];
        xout[o1] = n1 / (d1 + EPSF) + bias[co1];
        cout[o0] = d0 * winv[co0];
        cout[o1] = d1 * winv[co1];
    }
}

// ---------------------------------------------------------------------------
// Decoder normalized conv, 3x3, CIN=64 -> 32, fused concat + nearest 2x
// upsample: channels [0,32) come from group0, [32,64) from group1; a group
// flagged "half" is read at half resolution with (y>>1, x>>1) (i.e. up2()).
// ---------------------------------------------------------------------------
template <int HH, int WW>
__global__ __launch_bounds__(256)
void nconv_cat3_kernel(const float* __restrict__ x0p, const float* __restrict__ c0p, int half0,
                       const float* __restrict__ x1p, const float* __restrict__ c1p, int half1,
                       const float* __restrict__ w, const float* __restrict__ bias,
                       const float* __restrict__ winv,
                       float* __restrict__ xout, float* __restrict__ cout) {
    constexpr int KS = 3, PAD = 1, KK = 9, CIN = 64, CHUNK = 16;
    constexpr int W2 = WW / 2;
    __shared__ __align__(16) float ws[CHUNK * KK][32];

    const int tx = threadIdx.x & 15, ty = threadIdx.x >> 4;
    const int x = (blockIdx.x << 4) + tx;
    const int y = (blockIdx.y << 4) + ty;
    const int b = blockIdx.z;

    unsigned long long accN[16], accD[16];
#pragma unroll
    for (int i = 0; i < 16; i++) { accN[i] = 0ULL; accD[i] = 0ULL; }

    bool vy[KS], vx[KS];
#pragma unroll
    for (int k = 0; k < KS; k++) {
        vy[k] = (unsigned)(y + k - PAD) < (unsigned)HH;
        vx[k] = (unsigned)(x + k - PAD) < (unsigned)WW;
    }

    for (int ci0 = 0; ci0 < CIN; ci0 += CHUNK) {
        for (int i = threadIdx.x; i < CHUNK * KK * 32; i += 256)
            ws[i >> 5][i & 31] = w[((long)(i & 31) * CIN + ci0) * KK + (i >> 5)];
        __syncthreads();

        const int grp = ci0 >> 5;
        const float* xs = grp ? x1p : x0p;
        const float* cs = grp ? c1p : c0p;
        const int half = grp ? half1 : half0;
        const int cb = ci0 & 31;
        const long cstrideS = half ? (long)(HH / 2) * W2 : (long)HH * WW;

#pragma unroll 1
        for (int cil = 0; cil < CHUNK; cil++) {
            const float* xp = xs + ((long)b * 32 + cb + cil) * cstrideS;
            const float* cp = cs + ((long)b * 32 + cb + cil) * cstrideS;
#pragma unroll
            for (int ky = 0; ky < KS; ky++) {
#pragma unroll
                for (int kx = 0; kx < KS; kx++) {
                    const int yy = y + ky - PAD;
                    const int xx = x + kx - PAD;
                    const bool v = vy[ky] && vx[kx];
                    const long idx = half ? ((long)(yy >> 1) * W2 + (xx >> 1))
                                          : ((long)yy * WW + xx);
                    float cv = v ? __ldg(cp + idx) : 0.f;
                    float xv = v ? __ldg(xp + idx) : 0.f;
                    float xc = xv * cv;
                    unsigned long long xc2 = pack2(xc, xc);
                    unsigned long long cv2 = pack2(cv, cv);
                    const int kk = cil * KK + ky * KS + kx;
#pragma unroll
                    for (int q = 0; q < 8; q++) {
                        ulonglong2 wv = *reinterpret_cast<const ulonglong2*>(&ws[kk][q * 4]);
                        ffma2(accN[2 * q],     wv.x, xc2);
                        ffma2(accD[2 * q],     wv.x, cv2);
                        ffma2(accN[2 * q + 1], wv.y, xc2);
                        ffma2(accD[2 * q + 1], wv.y, cv2);
                    }
                }
            }
        }
        __syncthreads();
    }

    constexpr long PLANE = (long)HH * WW;
    const long pix = (long)y * WW + x;
#pragma unroll
    for (int q = 0; q < 16; q++) {
        float n0, n1, d0, d1;
        unpack2(accN[q], n0, n1);
        unpack2(accD[q], d0, d1);
        const int co0 = 2 * q, co1 = 2 * q + 1;
        const long o0 = ((long)b * 32 + co0) * PLANE + pix;
        const long o1 = o0 + PLANE;
        xout[o0] = n0 / (d0 + EPSF) + bias[co0];
        xout[o1] = n1 / (d1 + EPSF) + bias[co1];
        cout[o0] = d0 * winv[co0];
        cout[o1] = d1 * winv[co1];
    }
}

// ---------------------------------------------------------------------------
// 2x2 stride-2 confidence-argmax pool (first-occurrence argmax like jnp),
// gathers x at argmax, cout = cmax/4.
// ---------------------------------------------------------------------------
__global__ void pool_kernel(const float* __restrict__ xin, const float* __restrict__ cin,
                            float* __restrict__ xout, float* __restrict__ cout,
                            int Ho, int Wo) {
    long i = (long)blockIdx.x * blockDim.x + threadIdx.x;
    long total = 64L * Ho * Wo;  // 2 batches * 32 channels
    if (i >= total) return;
    int xo = (int)(i % Wo);
    long t = i / Wo;
    int yo = (int)(t % Ho);
    long bc = t / Ho;
    const int Wi = 2 * Wo;
    long ib = bc * 4L * Ho * Wo + (long)(2 * yo) * Wi + 2 * xo;
    float c00 = cin[ib], c01 = cin[ib + 1], c10 = cin[ib + Wi], c11 = cin[ib + Wi + 1];
    float best = c00; int bi = 0;
    if (c01 > best) { best = c01; bi = 1; }
    if (c10 > best) { best = c10; bi = 2; }
    if (c11 > best) { best = c11; bi = 3; }
    long off = (long)(bi >> 1) * Wi + (bi & 1);
    xout[i] = xin[ib + off];
    cout[i] = best * 0.25f;
}

// ---------------------------------------------------------------------------
// Final 1x1 nconv (32 -> 1): out = conv(x*c,w7)/(conv(c,w7)+eps) + b7
// ---------------------------------------------------------------------------
__global__ void final1x1_kernel(const float* __restrict__ xin, const float* __restrict__ cin,
                                const float* __restrict__ w7, const float* __restrict__ b7,
                                float* __restrict__ out) {
    constexpr long HW = 512L * 512L;
    long i = (long)blockIdx.x * blockDim.x + threadIdx.x;
    if (i >= 2 * HW) return;
    int b = (int)(i / HW);
    long p = i - (long)b * HW;
    const float* xb = xin + (long)b * 32 * HW + p;
    const float* cb = cin + (long)b * 32 * HW + p;
    float n = 0.f, d = 0.f;
#pragma unroll
    for (int ci = 0; ci < 32; ci++) {
        float wv = __ldg(w7 + ci);
        float cv = __ldg(cb + (long)ci * HW);
        float xv = __ldg(xb + (long)ci * HW);
        n += wv * xv * cv;
        d += wv * cv;
    }
    out[i] = n / (d + EPSF) + __ldg(b7);
}

// ---------------------------------------------------------------------------
// Launch sequence
// ---------------------------------------------------------------------------
extern "C" void kernel_launch(void* const* d_in, const int* in_sizes, int n_in,
                              void* d_out, int out_size) {
    const float* x  = (const float*)d_in[0];
    const float* w1 = (const float*)d_in[1];  const float* b1 = (const float*)d_in[2];
    const float* w2 = (const float*)d_in[3];  const float* b2 = (const float*)d_in[4];
    const float* w3 = (const float*)d_in[5];  const float* b3 = (const float*)d_in[6];
    const float* w4 = (const float*)d_in[7];  const float* b4 = (const float*)d_in[8];
    const float* w5 = (const float*)d_in[9];  const float* b5 = (const float*)d_in[10];
    const float* w6 = (const float*)d_in[11]; const float* b6 = (const float*)d_in[12];
    const float* w7 = (const float*)d_in[13]; const float* b7 = (const float*)d_in[14];

    float* pool = nullptr;
    cudaGetSymbolAddress((void**)&pool, g_pool);

    float* P0x = pool;
    float* P0c = pool + N512;
    float* P1x = pool + 2 * N512;
    float* P1c = pool + 3 * N512;
    float* X1  = pool + 4 * N512;
    float* C1  = pool + 5 * N512;
    float* X2  = pool + 6 * N512;
    float* C2  = X2 + N256;
    float* X3  = C2 + N256;
    float* C3  = X3 + N128;
    float* S0x = C3 + N128;
    float* S0c = S0x + N256;
    float* S1x = S0c + N256;
    float* S1c = S1x + N256;
    float* WS  = S1c + N256;

    const long HW = 512L * 512;

    wsum_kernel<<<7, 32>>>(w1, w2, w3, w4, w5, w6, w7, WS);

    // Encoder full-res: L1 (1->32), L2, L3 @512
    nconv_kernel<1, 5, 512, 512><<<dim3(32, 32, 2), 256>>>(
        x, x + HW, 2 * HW, HW, w1, b1, WS + 0, P0x, P0c);
    nconv_kernel<32, 5, 512, 512><<<dim3(32, 32, 2), 256>>>(
        P0x, P0c, 32 * HW, HW, w2, b2, WS + 32, P1x, P1c);
    nconv_kernel<32, 5, 512, 512><<<dim3(32, 32, 2), 256>>>(
        P1x, P1c, 32 * HW, HW, w3, b3, WS + 64, X1, C1);

    // Down 1: pool 512->256, L2, L3 @256
    pool_kernel<<<(int)((64L * 256 * 256 + 255) / 256), 256>>>(X1, C1, S0x, S0c, 256, 256);
    nconv_kernel<32, 5, 256, 256><<<dim3(16, 16, 2), 256>>>(
        S0x, S0c, 32L * 256 * 256, 256L * 256, w2, b2, WS + 32, S1x, S1c);
    nconv_kernel<32, 5, 256, 256><<<dim3(16, 16, 2), 256>>>(
        S1x, S1c, 32L * 256 * 256, 256L * 256, w3, b3, WS + 64, X2, C2);

    // Down 2: pool 256->128, L2 @128
    pool_kernel<<<(int)((64L * 128 * 128 + 255) / 256), 256>>>(X2, C2, S0x, S0c, 128, 128);
    nconv_kernel<32, 5, 128, 128><<<dim3(8, 8, 2), 256>>>(
        S0x, S0c, 32L * 128 * 128, 128L * 128, w2, b2, WS + 32, X3, C3);

    // Down 3: pool 128->64, L2 @64
    pool_kernel<<<(int)((64L * 64 * 64 + 255) / 256), 256>>>(X3, C3, S1x, S1c, 64, 64);
    nconv_kernel<32, 5, 64, 64><<<dim3(4, 4, 2), 256>>>(
        S1x, S1c, 32L * 64 * 64, 64L * 64, w2, b2, WS + 32, S0x, S0c);

    // Decoder: cat(x3_ds, up2(x4_ds)) @128 -> cat(x2_ds, up2(x34)) @256
    //          -> cat(up2(x23), x1) @512 -> 1x1
    nconv_cat3_kernel<128, 128><<<dim3(8, 8, 2), 256>>>(
        X3, C3, 0, S0x, S0c, 1, w4, b4, WS + 96, S1x, S1c);
    nconv_cat3_kernel<256, 256><<<dim3(16, 16, 2), 256>>>(
        X2, C2, 0, S1x, S1c, 1, w5, b5, WS + 128, S0x, S0c);
    nconv_cat3_kernel<512, 512><<<dim3(32, 32, 2), 256>>>(
        S0x, S0c, 1, X1, C1, 0, w6, b6, WS + 160, P0x, P0c);

    final1x1_kernel<<<2048, 256>>>(P0x, P0c, w7, b7, (float*)d_out);
}

// round 2
// speedup vs baseline: 1.2183x; 1.2183x over previous
#include <cuda_runtime.h>

#define EPSF 1e-20f

// ---------------------------------------------------------------------------
// Scratch pool (static __device__ memory — no allocations allowed).
// ---------------------------------------------------------------------------
static constexpr long N512 = 2L * 32 * 512 * 512;   // 16,777,216
static constexpr long N256 = 2L * 32 * 256 * 256;   //  4,194,304
static constexpr long N128 = 2L * 32 * 128 * 128;   //  1,048,576
static constexpr long POOL_FLOATS = 6 * N512 + 2 * N256 + 2 * N128 + 4 * N256 + 256;

__device__ float g_pool[POOL_FLOATS];

// ---------------------------------------------------------------------------
// Packed f32x2 helpers
// ---------------------------------------------------------------------------
__device__ __forceinline__ unsigned long long pack2(float a, float b) {
    unsigned long long r;
    asm("mov.b64 %0, {%1, %2};" : "=l"(r) : "f"(a), "f"(b));
    return r;
}
__device__ __forceinline__ void unpack2(unsigned long long v, float& a, float& b) {
    asm("mov.b64 {%0, %1}, %2;" : "=f"(a), "=f"(b) : "l"(v));
}
__device__ __forceinline__ void ffma2(unsigned long long& acc, unsigned long long w2,
                                      unsigned long long m2) {
    asm("fma.rn.f32x2 %0, %1, %2, %0;" : "+l"(acc) : "l"(w2), "l"(m2));
}

// ---------------------------------------------------------------------------
// Per-layer 1/sum(w): inv[l*32+co] = 1 / sum(w_l[co,:,:,:])
// ---------------------------------------------------------------------------
__global__ void wsum_kernel(const float* __restrict__ w1, const float* __restrict__ w2,
                            const float* __restrict__ w3, const float* __restrict__ w4,
                            const float* __restrict__ w5, const float* __restrict__ w6,
                            const float* __restrict__ w7, float* __restrict__ inv) {
    int l = blockIdx.x, co = threadIdx.x;
    const float* w; int n; int nco = 32;
    if      (l == 0) { w = w1; n = 1 * 25; }
    else if (l == 1) { w = w2; n = 32 * 25; }
    else if (l == 2) { w = w3; n = 32 * 25; }
    else if (l == 3) { w = w4; n = 64 * 9; }
    else if (l == 4) { w = w5; n = 64 * 9; }
    else if (l == 5) { w = w6; n = 64 * 9; }
    else             { w = w7; n = 32;  nco = 1; }
    if (co >= nco) return;
    float s = 0.f;
    for (int i = 0; i < n; i++) s += w[co * n + i];
    inv[l * 32 + co] = 1.0f / s;
}

// ---------------------------------------------------------------------------
// Fast normalized conv: KSxKS, CIN -> 32, same-padding.
// Block = 256 threads: 128 pixel-slots (32 wide x 4 slot-rows, 2 vertically
// adjacent pixels per slot) x 2 output-channel groups (16 co each).
// Inputs staged per-ci in shared (tile+halo); input column registers reused
// across ky and both pixels; weights read as broadcast LDS.128.
// ---------------------------------------------------------------------------
template <int CIN, int KS, int HH, int WW, int CHUNK>
__global__ __launch_bounds__(256)
void nconv_fast(const float* __restrict__ xin, const float* __restrict__ cin,
                long bstride, long cstride,
                const float* __restrict__ w, const float* __restrict__ bias,
                const float* __restrict__ winv,
                float* __restrict__ xout, float* __restrict__ cout) {
    constexpr int PAD = KS / 2, KK = KS * KS;
    constexpr int TW = 32, TH = 8;
    constexpr int SW = TW + KS - 1, SH = TH + KS - 1;
    constexpr int NROW = KS + 1;   // input rows per thread window (2 pixels)
    __shared__ __align__(16) float ws[CHUNK * KK][32];
    __shared__ float cs[SH * SW];
    __shared__ float xcs[SH * SW];

    const int tid = threadIdx.x;
    const int cg = tid >> 7;            // 0 or 1 (co group)
    const int t = tid & 127;
    const int tx = t & 31;
    const int ry = (t >> 5) * 2;        // 0,2,4,6
    const int bx = blockIdx.x * TW, by = blockIdx.y * TH;
    const int b = blockIdx.z;

    unsigned long long accN[2][8], accD[2][8];
#pragma unroll
    for (int p = 0; p < 2; p++)
#pragma unroll
        for (int q = 0; q < 8; q++) { accN[p][q] = 0ULL; accD[p][q] = 0ULL; }

    const int sbase = ry * SW + tx;

#pragma unroll 1
    for (int ci0 = 0; ci0 < CIN; ci0 += CHUNK) {
        __syncthreads();
        for (int i = tid; i < CHUNK * KK * 32; i += 256)
            ws[i >> 5][i & 31] = w[((long)(i & 31) * CIN + ci0) * KK + (i >> 5)];

#pragma unroll 1
        for (int cil = 0; cil < CHUNK; cil++) {
            __syncthreads();
            {
                const float* xp = xin + (long)b * bstride + (long)(ci0 + cil) * cstride;
                const float* cp = cin + (long)b * bstride + (long)(ci0 + cil) * cstride;
                for (int i = tid; i < SH * SW; i += 256) {
                    int r = i / SW, c = i - r * SW;
                    int gy = by + r - PAD, gx = bx + c - PAD;
                    float cv = 0.f, xv = 0.f;
                    if ((unsigned)gy < (unsigned)HH && (unsigned)gx < (unsigned)WW) {
                        long g = (long)gy * WW + gx;
                        cv = __ldg(cp + g);
                        xv = __ldg(xp + g);
                    }
                    cs[i] = cv;
                    xcs[i] = xv * cv;
                }
            }
            __syncthreads();

#pragma unroll
            for (int kx = 0; kx < KS; kx++) {
                unsigned long long c2[NROW], x2[NROW];
#pragma unroll
                for (int r = 0; r < NROW; r++) {
                    float cv = cs[sbase + r * SW + kx];
                    float xc = xcs[sbase + r * SW + kx];
                    c2[r] = pack2(cv, cv);
                    x2[r] = pack2(xc, xc);
                }
#pragma unroll
                for (int ky = 0; ky < KS; ky++) {
                    const int kk = cil * KK + ky * KS + kx;
                    const float* wrow = &ws[kk][cg * 16];
                    ulonglong2 w0 = *reinterpret_cast<const ulonglong2*>(wrow);
                    ulonglong2 w1 = *reinterpret_cast<const ulonglong2*>(wrow + 4);
                    ulonglong2 w2 = *reinterpret_cast<const ulonglong2*>(wrow + 8);
                    ulonglong2 w3 = *reinterpret_cast<const ulonglong2*>(wrow + 12);
#pragma unroll
                    for (int p = 0; p < 2; p++) {
                        unsigned long long xc2 = x2[ky + p], cv2 = c2[ky + p];
                        ffma2(accN[p][0], w0.x, xc2); ffma2(accD[p][0], w0.x, cv2);
                        ffma2(accN[p][1], w0.y, xc2); ffma2(accD[p][1], w0.y, cv2);
                        ffma2(accN[p][2], w1.x, xc2); ffma2(accD[p][2], w1.x, cv2);
                        ffma2(accN[p][3], w1.y, xc2); ffma2(accD[p][3], w1.y, cv2);
                        ffma2(accN[p][4], w2.x, xc2); ffma2(accD[p][4], w2.x, cv2);
                        ffma2(accN[p][5], w2.y, xc2); ffma2(accD[p][5], w2.y, cv2);
                        ffma2(accN[p][6], w3.x, xc2); ffma2(accD[p][6], w3.x, cv2);
                        ffma2(accN[p][7], w3.y, xc2); ffma2(accD[p][7], w3.y, cv2);
                    }
                }
            }
        }
    }

    constexpr long PLANE = (long)HH * WW;
    const int xg = bx + tx;
#pragma unroll
    for (int p = 0; p < 2; p++) {
        const int yg = by + ry + p;
        const long pix = (long)yg * WW + xg;
#pragma unroll
        for (int q = 0; q < 8; q++) {
            float n0, n1, d0, d1;
            unpack2(accN[p][q], n0, n1);
            unpack2(accD[p][q], d0, d1);
            const int co0 = cg * 16 + 2 * q;
            const long o0 = ((long)b * 32 + co0) * PLANE + pix;
            xout[o0]         = n0 / (d0 + EPSF) + bias[co0];
            xout[o0 + PLANE] = n1 / (d1 + EPSF) + bias[co0 + 1];
            cout[o0]         = d0 * winv[co0];
            cout[o0 + PLANE] = d1 * winv[co0 + 1];
        }
    }
}

// ---------------------------------------------------------------------------
// Decoder fast nconv: 3x3, CIN=64 -> 32, fused concat + nearest-2x upsample.
// Same blocking as nconv_fast. Group flagged "half" is read at half res.
// ---------------------------------------------------------------------------
template <int HH, int WW>
__global__ __launch_bounds__(256)
void nconv_cat_fast(const float* __restrict__ x0p, const float* __restrict__ c0p, int half0,
                    const float* __restrict__ x1p, const float* __restrict__ c1p, int half1,
                    const float* __restrict__ w, const float* __restrict__ bias,
                    const float* __restrict__ winv,
                    float* __restrict__ xout, float* __restrict__ cout) {
    constexpr int KS = 3, PAD = 1, KK = 9, CIN = 64, CHUNK = 16;
    constexpr int TW = 32, TH = 8;
    constexpr int SW = TW + KS - 1, SH = TH + KS - 1;
    constexpr int NROW = KS + 1;
    constexpr int W2 = WW / 2;
    __shared__ __align__(16) float ws[CHUNK * KK][32];
    __shared__ float cs[SH * SW];
    __shared__ float xcs[SH * SW];

    const int tid = threadIdx.x;
    const int cg = tid >> 7;
    const int t = tid & 127;
    const int tx = t & 31;
    const int ry = (t >> 5) * 2;
    const int bx = blockIdx.x * TW, by = blockIdx.y * TH;
    const int b = blockIdx.z;

    unsigned long long accN[2][8], accD[2][8];
#pragma unroll
    for (int p = 0; p < 2; p++)
#pragma unroll
        for (int q = 0; q < 8; q++) { accN[p][q] = 0ULL; accD[p][q] = 0ULL; }

    const int sbase = ry * SW + tx;

#pragma unroll 1
    for (int ci0 = 0; ci0 < CIN; ci0 += CHUNK) {
        __syncthreads();
        for (int i = tid; i < CHUNK * KK * 32; i += 256)
            ws[i >> 5][i & 31] = w[((long)(i & 31) * CIN + ci0) * KK + (i >> 5)];

#pragma unroll 1
        for (int cil = 0; cil < CHUNK; cil++) {
            const int ci = ci0 + cil;
            const int grp = ci >> 5;
            const float* xs = grp ? x1p : x0p;
            const float* cp_ = grp ? c1p : c0p;
            const int half = grp ? half1 : half0;
            const long plane = half ? (long)(HH / 2) * W2 : (long)HH * WW;
            const float* xp = xs + ((long)b * 32 + (ci & 31)) * plane;
            const float* cp = cp_ + ((long)b * 32 + (ci & 31)) * plane;

            __syncthreads();
            for (int i = tid; i < SH * SW; i += 256) {
                int r = i / SW, c = i - r * SW;
                int gy = by + r - PAD, gx = bx + c - PAD;
                float cv = 0.f, xv = 0.f;
                if ((unsigned)gy < (unsigned)HH && (unsigned)gx < (unsigned)WW) {
                    long g = half ? ((long)(gy >> 1) * W2 + (gx >> 1))
                                  : ((long)gy * WW + gx);
                    cv = __ldg(cp + g);
                    xv = __ldg(xp + g);
                }
                cs[i] = cv;
                xcs[i] = xv * cv;
            }
            __syncthreads();

#pragma unroll
            for (int kx = 0; kx < KS; kx++) {
                unsigned long long c2[NROW], x2[NROW];
#pragma unroll
                for (int r = 0; r < NROW; r++) {
                    float cv = cs[sbase + r * SW + kx];
                    float xc = xcs[sbase + r * SW + kx];
                    c2[r] = pack2(cv, cv);
                    x2[r] = pack2(xc, xc);
                }
#pragma unroll
                for (int ky = 0; ky < KS; ky++) {
                    const int kk = cil * KK + ky * KS + kx;
                    const float* wrow = &ws[kk][cg * 16];
                    ulonglong2 w0 = *reinterpret_cast<const ulonglong2*>(wrow);
                    ulonglong2 w1 = *reinterpret_cast<const ulonglong2*>(wrow + 4);
                    ulonglong2 w2 = *reinterpret_cast<const ulonglong2*>(wrow + 8);
                    ulonglong2 w3 = *reinterpret_cast<const ulonglong2*>(wrow + 12);
#pragma unroll
                    for (int p = 0; p < 2; p++) {
                        unsigned long long xc2 = x2[ky + p], cv2 = c2[ky + p];
                        ffma2(accN[p][0], w0.x, xc2); ffma2(accD[p][0], w0.x, cv2);
                        ffma2(accN[p][1], w0.y, xc2); ffma2(accD[p][1], w0.y, cv2);
                        ffma2(accN[p][2], w1.x, xc2); ffma2(accD[p][2], w1.x, cv2);
                        ffma2(accN[p][3], w1.y, xc2); ffma2(accD[p][3], w1.y, cv2);
                        ffma2(accN[p][4], w2.x, xc2); ffma2(accD[p][4], w2.x, cv2);
                        ffma2(accN[p][5], w2.y, xc2); ffma2(accD[p][5], w2.y, cv2);
                        ffma2(accN[p][6], w3.x, xc2); ffma2(accD[p][6], w3.x, cv2);
                        ffma2(accN[p][7], w3.y, xc2); ffma2(accD[p][7], w3.y, cv2);
                    }
                }
            }
        }
    }

    constexpr long PLANE = (long)HH * WW;
    const int xg = bx + tx;
#pragma unroll
    for (int p = 0; p < 2; p++) {
        const int yg = by + ry + p;
        const long pix = (long)yg * WW + xg;
#pragma unroll
        for (int q = 0; q < 8; q++) {
            float n0, n1, d0, d1;
            unpack2(accN[p][q], n0, n1);
            unpack2(accD[p][q], d0, d1);
            const int co0 = cg * 16 + 2 * q;
            const long o0 = ((long)b * 32 + co0) * PLANE + pix;
            xout[o0]         = n0 / (d0 + EPSF) + bias[co0];
            xout[o0 + PLANE] = n1 / (d1 + EPSF) + bias[co0 + 1];
            cout[o0]         = d0 * winv[co0];
            cout[o0 + PLANE] = d1 * winv[co0 + 1];
        }
    }
}

// ---------------------------------------------------------------------------
// 2x2 stride-2 confidence-argmax pool (first-occurrence argmax like jnp).
// ---------------------------------------------------------------------------
__global__ void pool_kernel(const float* __restrict__ xin, const float* __restrict__ cin,
                            float* __restrict__ xout, float* __restrict__ cout,
                            int Ho, int Wo) {
    long i = (long)blockIdx.x * blockDim.x + threadIdx.x;
    long total = 64L * Ho * Wo;
    if (i >= total) return;
    int xo = (int)(i % Wo);
    long t = i / Wo;
    int yo = (int)(t % Ho);
    long bc = t / Ho;
    const int Wi = 2 * Wo;
    long ib = bc * 4L * Ho * Wo + (long)(2 * yo) * Wi + 2 * xo;
    float c00 = cin[ib], c01 = cin[ib + 1], c10 = cin[ib + Wi], c11 = cin[ib + Wi + 1];
    float best = c00; int bi = 0;
    if (c01 > best) { best = c01; bi = 1; }
    if (c10 > best) { best = c10; bi = 2; }
    if (c11 > best) { best = c11; bi = 3; }
    long off = (long)(bi >> 1) * Wi + (bi & 1);
    xout[i] = xin[ib + off];
    cout[i] = best * 0.25f;
}

// ---------------------------------------------------------------------------
// Final 1x1 nconv (32 -> 1)
// ---------------------------------------------------------------------------
__global__ void final1x1_kernel(const float* __restrict__ xin, const float* __restrict__ cin,
                                const float* __restrict__ w7, const float* __restrict__ b7,
                                float* __restrict__ out) {
    constexpr long HW = 512L * 512L;
    long i = (long)blockIdx.x * blockDim.x + threadIdx.x;
    if (i >= 2 * HW) return;
    int b = (int)(i / HW);
    long p = i - (long)b * HW;
    const float* xb = xin + (long)b * 32 * HW + p;
    const float* cb = cin + (long)b * 32 * HW + p;
    float n = 0.f, d = 0.f;
#pragma unroll
    for (int ci = 0; ci < 32; ci++) {
        float wv = __ldg(w7 + ci);
        float cv = __ldg(cb + (long)ci * HW);
        float xv = __ldg(xb + (long)ci * HW);
        n += wv * xv * cv;
        d += wv * cv;
    }
    out[i] = n / (d + EPSF) + __ldg(b7);
}

// ---------------------------------------------------------------------------
// Launch sequence
// ---------------------------------------------------------------------------
extern "C" void kernel_launch(void* const* d_in, const int* in_sizes, int n_in,
                              void* d_out, int out_size) {
    const float* x  = (const float*)d_in[0];
    const float* w1 = (const float*)d_in[1];  const float* b1 = (const float*)d_in[2];
    const float* w2 = (const float*)d_in[3];  const float* b2 = (const float*)d_in[4];
    const float* w3 = (const float*)d_in[5];  const float* b3 = (const float*)d_in[6];
    const float* w4 = (const float*)d_in[7];  const float* b4 = (const float*)d_in[8];
    const float* w5 = (const float*)d_in[9];  const float* b5 = (const float*)d_in[10];
    const float* w6 = (const float*)d_in[11]; const float* b6 = (const float*)d_in[12];
    const float* w7 = (const float*)d_in[13]; const float* b7 = (const float*)d_in[14];

    float* pool = nullptr;
    cudaGetSymbolAddress((void**)&pool, g_pool);

    float* P0x = pool;
    float* P0c = pool + N512;
    float* P1x = pool + 2 * N512;
    float* P1c = pool + 3 * N512;
    float* X1  = pool + 4 * N512;
    float* C1  = pool + 5 * N512;
    float* X2  = pool + 6 * N512;
    float* C2  = X2 + N256;
    float* X3  = C2 + N256;
    float* C3  = X3 + N128;
    float* S0x = C3 + N128;
    float* S0c = S0x + N256;
    float* S1x = S0c + N256;
    float* S1c = S1x + N256;
    float* WS  = S1c + N256;

    const long HW = 512L * 512;

    wsum_kernel<<<7, 32>>>(w1, w2, w3, w4, w5, w6, w7, WS);

    // Encoder full-res: L1 (1->32), L2, L3 @512
    nconv_fast<1, 5, 512, 512, 1><<<dim3(16, 64, 2), 256>>>(
        x, x + HW, 2 * HW, HW, w1, b1, WS + 0, P0x, P0c);
    nconv_fast<32, 5, 512, 512, 8><<<dim3(16, 64, 2), 256>>>(
        P0x, P0c, 32 * HW, HW, w2, b2, WS + 32, P1x, P1c);
    nconv_fast<32, 5, 512, 512, 8><<<dim3(16, 64, 2), 256>>>(
        P1x, P1c, 32 * HW, HW, w3, b3, WS + 64, X1, C1);

    // Down 1: pool 512->256, L2, L3 @256
    pool_kernel<<<(int)((64L * 256 * 256 + 255) / 256), 256>>>(X1, C1, S0x, S0c, 256, 256);
    nconv_fast<32, 5, 256, 256, 8><<<dim3(8, 32, 2), 256>>>(
        S0x, S0c, 32L * 256 * 256, 256L * 256, w2, b2, WS + 32, S1x, S1c);
    nconv_fast<32, 5, 256, 256, 8><<<dim3(8, 32, 2), 256>>>(
        S1x, S1c, 32L * 256 * 256, 256L * 256, w3, b3, WS + 64, X2, C2);

    // Down 2: pool 256->128, L2 @128
    pool_kernel<<<(int)((64L * 128 * 128 + 255) / 256), 256>>>(X2, C2, S0x, S0c, 128, 128);
    nconv_fast<32, 5, 128, 128, 8><<<dim3(4, 16, 2), 256>>>(
        S0x, S0c, 32L * 128 * 128, 128L * 128, w2, b2, WS + 32, X3, C3);

    // Down 3: pool 128->64, L2 @64
    pool_kernel<<<(int)((64L * 64 * 64 + 255) / 256), 256>>>(X3, C3, S1x, S1c, 64, 64);
    nconv_fast<32, 5, 64, 64, 8><<<dim3(2, 8, 2), 256>>>(
        S1x, S1c, 32L * 64 * 64, 64L * 64, w2, b2, WS + 32, S0x, S0c);

    // Decoder
    nconv_cat_fast<128, 128><<<dim3(4, 16, 2), 256>>>(
        X3, C3, 0, S0x, S0c, 1, w4, b4, WS + 96, S1x, S1c);
    nconv_cat_fast<256, 256><<<dim3(8, 32, 2), 256>>>(
        X2, C2, 0, S1x, S1c, 1, w5, b5, WS + 128, S0x, S0c);
    nconv_cat_fast<512, 512><<<dim3(16, 64, 2), 256>>>(
        S0x, S0c, 1, X1, C1, 0, w6, b6, WS + 160, P0x, P0c);

    final1x1_kernel<<<2048, 256>>>(P0x, P0c, w7, b7, (float*)d_out);
}

// round 3
// speedup vs baseline: 1.3203x; 1.0837x over previous
#include <cuda_runtime.h>

#define EPSF 1e-20f

// ---------------------------------------------------------------------------
// Scratch pool (static __device__ memory — no allocations allowed).
// ---------------------------------------------------------------------------
static constexpr long N512 = 2L * 32 * 512 * 512;
static constexpr long N256 = 2L * 32 * 256 * 256;
static constexpr long N128 = 2L * 32 * 128 * 128;
static constexpr long POOL_FLOATS = 6 * N512 + 2 * N256 + 2 * N128 + 4 * N256 + 256;

__device__ float g_pool[POOL_FLOATS];

// ---------------------------------------------------------------------------
// Packed f32x2 helpers
// ---------------------------------------------------------------------------
__device__ __forceinline__ unsigned long long pack2(float a, float b) {
    unsigned long long r;
    asm("mov.b64 %0, {%1, %2};" : "=l"(r) : "f"(a), "f"(b));
    return r;
}
__device__ __forceinline__ void unpack2(unsigned long long v, float& a, float& b) {
    asm("mov.b64 {%0, %1}, %2;" : "=f"(a), "=f"(b) : "l"(v));
}
__device__ __forceinline__ void ffma2(unsigned long long& acc, unsigned long long w2,
                                      unsigned long long m2) {
    asm("fma.rn.f32x2 %0, %1, %2, %0;" : "+l"(acc) : "l"(w2), "l"(m2));
}

// ---------------------------------------------------------------------------
// cp.async helpers (LDGSTS)
// ---------------------------------------------------------------------------
__device__ __forceinline__ void cp_async4(unsigned dst, const float* src, bool valid) {
    int sz = valid ? 4 : 0;
    asm volatile("cp.async.ca.shared.global [%0], [%1], 4, %2;\n"
                 :: "r"(dst), "l"(src), "r"(sz));
}
__device__ __forceinline__ void cp_commit() {
    asm volatile("cp.async.commit_group;\n");
}
template <int N>
__device__ __forceinline__ void cp_wait() {
    asm volatile("cp.async.wait_group %0;\n" :: "n"(N));
}

// ---------------------------------------------------------------------------
// Per-layer 1/sum(w): inv[l*32+co] = 1 / sum(w_l[co,:,:,:])
// ---------------------------------------------------------------------------
__global__ void wsum_kernel(const float* __restrict__ w1, const float* __restrict__ w2,
                            const float* __restrict__ w3, const float* __restrict__ w4,
                            const float* __restrict__ w5, const float* __restrict__ w6,
                            const float* __restrict__ w7, float* __restrict__ inv) {
    int l = blockIdx.x, co = threadIdx.x;
    const float* w; int n; int nco = 32;
    if      (l == 0) { w = w1; n = 1 * 25; }
    else if (l == 1) { w = w2; n = 32 * 25; }
    else if (l == 2) { w = w3; n = 32 * 25; }
    else if (l == 3) { w = w4; n = 64 * 9; }
    else if (l == 4) { w = w5; n = 64 * 9; }
    else if (l == 5) { w = w6; n = 64 * 9; }
    else             { w = w7; n = 32;  nco = 1; }
    if (co >= nco) return;
    float s = 0.f;
    for (int i = 0; i < n; i++) s += w[co * n + i];
    inv[l * 32 + co] = 1.0f / s;
}

// ---------------------------------------------------------------------------
// Fast normalized conv: KSxKS, CIN -> 32, same-padding.
// Block = 256 threads: 128 pixel-slots (32w x 4 slot-rows, 2 vertical pixels
// per slot) x 2 co-groups of 16. Raw x,c tiles double-buffered via cp.async;
// weights chunk-staged via cp.async; one barrier per input channel.
// ---------------------------------------------------------------------------
template <int CIN, int KS, int HH, int WW, int CHUNK>
__global__ __launch_bounds__(256)
void nconv_fast(const float* __restrict__ xin, const float* __restrict__ cin,
                long bstride, long cstride,
                const float* __restrict__ w, const float* __restrict__ bias,
                const float* __restrict__ winv,
                float* __restrict__ xout, float* __restrict__ cout) {
    constexpr int PAD = KS / 2, KK = KS * KS;
    constexpr int TW = 32, TH = 8;
    constexpr int SW = TW + KS - 1, SH = TH + KS - 1, NS = SH * SW;
    constexpr int NROW = KS + 1;
    __shared__ __align__(16) float ws[CHUNK * KK][32];
    __shared__ __align__(16) float cbuf[2][NS];
    __shared__ __align__(16) float xbuf[2][NS];

    const int tid = threadIdx.x;
    const int cg = tid >> 7;
    const int t = tid & 127;
    const int tx = t & 31;
    const int ry = (t >> 5) * 2;
    const int bx = blockIdx.x * TW, by = blockIdx.y * TH;
    const int b = blockIdx.z;

    unsigned long long accN[2][8], accD[2][8];
#pragma unroll
    for (int p = 0; p < 2; p++)
#pragma unroll
        for (int q = 0; q < 8; q++) { accN[p][q] = 0ULL; accD[p][q] = 0ULL; }

    const int sbase = ry * SW + tx;

    // Per-thread staging elements (<= 2 each; NS <= 512)
    const int i0 = tid, i1 = tid + 256;
    long g0 = 0, g1 = 0; bool v0 = false, v1 = false;
    {
        int r = i0 / SW, c = i0 - r * SW;
        int gy = by + r - PAD, gx = bx + c - PAD;
        v0 = (unsigned)gy < (unsigned)HH && (unsigned)gx < (unsigned)WW;
        g0 = v0 ? (long)gy * WW + gx : 0;
        if (i1 < NS) {
            r = i1 / SW; c = i1 - r * SW;
            gy = by + r - PAD; gx = bx + c - PAD;
            v1 = (unsigned)gy < (unsigned)HH && (unsigned)gx < (unsigned)WW;
            g1 = v1 ? (long)gy * WW + gx : 0;
        }
    }

    const unsigned ws_s = (unsigned)__cvta_generic_to_shared(&ws[0][0]);
    unsigned c_s[2], x_s[2];
    c_s[0] = (unsigned)__cvta_generic_to_shared(&cbuf[0][0]);
    c_s[1] = (unsigned)__cvta_generic_to_shared(&cbuf[1][0]);
    x_s[0] = (unsigned)__cvta_generic_to_shared(&xbuf[0][0]);
    x_s[1] = (unsigned)__cvta_generic_to_shared(&xbuf[1][0]);

    const float* xb = xin + (long)b * bstride;
    const float* cb = cin + (long)b * bstride;

    // Prefetch ci = 0
    {
        cp_async4(c_s[0] + i0 * 4, cb + g0, v0);
        cp_async4(x_s[0] + i0 * 4, xb + g0, v0);
        if (i1 < NS) {
            cp_async4(c_s[0] + i1 * 4, cb + g1, v1);
            cp_async4(x_s[0] + i1 * 4, xb + g1, v1);
        }
        cp_commit();
    }

#pragma unroll 1
    for (int ci = 0; ci < CIN; ci++) {
        const int bufc = ci & 1;
        const int cil = ci & (CHUNK - 1);
        cp_wait<0>();
        __syncthreads();

        if (cil == 0) {  // stage this chunk's weights (async)
            for (int i = tid; i < CHUNK * KK * 32; i += 256)
                cp_async4(ws_s + i * 4u,
                          w + ((long)(i & 31) * CIN + ci) * KK + (i >> 5), true);
            cp_commit();
        }
        if (ci + 1 < CIN) {  // prefetch next input channel
            const float* cp = cb + (long)(ci + 1) * cstride;
            const float* xp = xb + (long)(ci + 1) * cstride;
            const int nb = bufc ^ 1;
            cp_async4(c_s[nb] + i0 * 4, cp + g0, v0);
            cp_async4(x_s[nb] + i0 * 4, xp + g0, v0);
            if (i1 < NS) {
                cp_async4(c_s[nb] + i1 * 4, cp + g1, v1);
                cp_async4(x_s[nb] + i1 * 4, xp + g1, v1);
            }
            cp_commit();
        }
        if (cil == 0) {  // weights must land before compute
            if (ci + 1 < CIN) cp_wait<1>(); else cp_wait<0>();
            __syncthreads();
        }

        const float* csb = cbuf[bufc];
        const float* xsb = xbuf[bufc];
#pragma unroll
        for (int kx = 0; kx < KS; kx++) {
            unsigned long long c2[NROW], x2[NROW];
#pragma unroll
            for (int r = 0; r < NROW; r++) {
                float cv = csb[sbase + r * SW + kx];
                float xv = xsb[sbase + r * SW + kx];
                float xc = xv * cv;
                c2[r] = pack2(cv, cv);
                x2[r] = pack2(xc, xc);
            }
#pragma unroll
            for (int ky = 0; ky < KS; ky++) {
                const int kk = cil * KK + ky * KS + kx;
                const float* wrow = &ws[kk][cg * 16];
                ulonglong2 w0 = *reinterpret_cast<const ulonglong2*>(wrow);
                ulonglong2 w1 = *reinterpret_cast<const ulonglong2*>(wrow + 4);
                ulonglong2 w2 = *reinterpret_cast<const ulonglong2*>(wrow + 8);
                ulonglong2 w3 = *reinterpret_cast<const ulonglong2*>(wrow + 12);
#pragma unroll
                for (int p = 0; p < 2; p++) {
                    unsigned long long xc2 = x2[ky + p], cv2 = c2[ky + p];
                    ffma2(accN[p][0], w0.x, xc2); ffma2(accD[p][0], w0.x, cv2);
                    ffma2(accN[p][1], w0.y, xc2); ffma2(accD[p][1], w0.y, cv2);
                    ffma2(accN[p][2], w1.x, xc2); ffma2(accD[p][2], w1.x, cv2);
                    ffma2(accN[p][3], w1.y, xc2); ffma2(accD[p][3], w1.y, cv2);
                    ffma2(accN[p][4], w2.x, xc2); ffma2(accD[p][4], w2.x, cv2);
                    ffma2(accN[p][5], w2.y, xc2); ffma2(accD[p][5], w2.y, cv2);
                    ffma2(accN[p][6], w3.x, xc2); ffma2(accD[p][6], w3.x, cv2);
                    ffma2(accN[p][7], w3.y, xc2); ffma2(accD[p][7], w3.y, cv2);
                }
            }
        }
    }

    constexpr long PLANE = (long)HH * WW;
    const int xg = bx + tx;
#pragma unroll
    for (int p = 0; p < 2; p++) {
        const int yg = by + ry + p;
        const long pix = (long)yg * WW + xg;
#pragma unroll
        for (int q = 0; q < 8; q++) {
            float n0, n1, d0, d1;
            unpack2(accN[p][q], n0, n1);
            unpack2(accD[p][q], d0, d1);
            const int co0 = cg * 16 + 2 * q;
            const long o0 = ((long)b * 32 + co0) * PLANE + pix;
            xout[o0]         = n0 / (d0 + EPSF) + bias[co0];
            xout[o0 + PLANE] = n1 / (d1 + EPSF) + bias[co0 + 1];
            cout[o0]         = d0 * winv[co0];
            cout[o0 + PLANE] = d1 * winv[co0 + 1];
        }
    }
}

// ---------------------------------------------------------------------------
// Decoder fast nconv: 3x3, CIN=64 -> 32, fused concat + nearest-2x upsample,
// same cp.async double-buffered pipeline. Group flagged "half" reads half-res.
// ---------------------------------------------------------------------------
template <int HH, int WW>
__global__ __launch_bounds__(256)
void nconv_cat_fast(const float* __restrict__ x0p, const float* __restrict__ c0p, int half0,
                    const float* __restrict__ x1p, const float* __restrict__ c1p, int half1,
                    const float* __restrict__ w, const float* __restrict__ bias,
                    const float* __restrict__ winv,
                    float* __restrict__ xout, float* __restrict__ cout) {
    constexpr int KS = 3, PAD = 1, KK = 9, CIN = 64, CHUNK = 16;
    constexpr int TW = 32, TH = 8;
    constexpr int SW = TW + KS - 1, SH = TH + KS - 1, NS = SH * SW;
    constexpr int NROW = KS + 1;
    constexpr int W2 = WW / 2;
    __shared__ __align__(16) float ws[CHUNK * KK][32];
    __shared__ __align__(16) float cbuf[2][NS];
    __shared__ __align__(16) float xbuf[2][NS];

    const int tid = threadIdx.x;
    const int cg = tid >> 7;
    const int t = tid & 127;
    const int tx = t & 31;
    const int ry = (t >> 5) * 2;
    const int bx = blockIdx.x * TW, by = blockIdx.y * TH;
    const int b = blockIdx.z;

    unsigned long long accN[2][8], accD[2][8];
#pragma unroll
    for (int p = 0; p < 2; p++)
#pragma unroll
        for (int q = 0; q < 8; q++) { accN[p][q] = 0ULL; accD[p][q] = 0ULL; }

    const int sbase = ry * SW + tx;

    // Per-thread staging elements: full-res and half-res gather offsets
    const int i0 = tid, i1 = tid + 256;
    long g0F = 0, g0H = 0, g1F = 0, g1H = 0; bool v0 = false, v1 = false;
    if (i0 < NS) {
        int r = i0 / SW, c = i0 - r * SW;
        int gy = by + r - PAD, gx = bx + c - PAD;
        v0 = (unsigned)gy < (unsigned)HH && (unsigned)gx < (unsigned)WW;
        g0F = v0 ? (long)gy * WW + gx : 0;
        g0H = v0 ? (long)(gy >> 1) * W2 + (gx >> 1) : 0;
    }
    if (i1 < NS) {
        int r = i1 / SW, c = i1 - r * SW;
        int gy = by + r - PAD, gx = bx + c - PAD;
        v1 = (unsigned)gy < (unsigned)HH && (unsigned)gx < (unsigned)WW;
        g1F = v1 ? (long)gy * WW + gx : 0;
        g1H = v1 ? (long)(gy >> 1) * W2 + (gx >> 1) : 0;
    }

    const unsigned ws_s = (unsigned)__cvta_generic_to_shared(&ws[0][0]);
    unsigned c_s[2], x_s[2];
    c_s[0] = (unsigned)__cvta_generic_to_shared(&cbuf[0][0]);
    c_s[1] = (unsigned)__cvta_generic_to_shared(&cbuf[1][0]);
    x_s[0] = (unsigned)__cvta_generic_to_shared(&xbuf[0][0]);
    x_s[1] = (unsigned)__cvta_generic_to_shared(&xbuf[1][0]);

    // prefetch helper (inlined): channel ci into buffer nb
    auto prefetch = [&](int ci, int nb) {
        const int grp = ci >> 5;
        const float* xs = grp ? x1p : x0p;
        const float* cc = grp ? c1p : c0p;
        const int half = grp ? half1 : half0;
        const long plane = half ? (long)(HH / 2) * W2 : (long)HH * WW;
        const float* xp = xs + ((long)b * 32 + (ci & 31)) * plane;
        const float* cp = cc + ((long)b * 32 + (ci & 31)) * plane;
        const long o0 = half ? g0H : g0F;
        const long o1 = half ? g1H : g1F;
        if (i0 < NS) {
            cp_async4(c_s[nb] + i0 * 4, cp + o0, v0);
            cp_async4(x_s[nb] + i0 * 4, xp + o0, v0);
        }
        if (i1 < NS) {
            cp_async4(c_s[nb] + i1 * 4, cp + o1, v1);
            cp_async4(x_s[nb] + i1 * 4, xp + o1, v1);
        }
        cp_commit();
    };

    prefetch(0, 0);

#pragma unroll 1
    for (int ci = 0; ci < CIN; ci++) {
        const int bufc = ci & 1;
        const int cil = ci & (CHUNK - 1);
        cp_wait<0>();
        __syncthreads();

        if (cil == 0) {
            for (int i = tid; i < CHUNK * KK * 32; i += 256)
                cp_async4(ws_s + i * 4u,
                          w + ((long)(i & 31) * CIN + ci) * KK + (i >> 5), true);
            cp_commit();
        }
        if (ci + 1 < CIN) prefetch(ci + 1, bufc ^ 1);
        if (cil == 0) {
            if (ci + 1 < CIN) cp_wait<1>(); else cp_wait<0>();
            __syncthreads();
        }

        const float* csb = cbuf[bufc];
        const float* xsb = xbuf[bufc];
#pragma unroll
        for (int kx = 0; kx < KS; kx++) {
            unsigned long long c2[NROW], x2[NROW];
#pragma unroll
            for (int r = 0; r < NROW; r++) {
                float cv = csb[sbase + r * SW + kx];
                float xv = xsb[sbase + r * SW + kx];
                float xc = xv * cv;
                c2[r] = pack2(cv, cv);
                x2[r] = pack2(xc, xc);
            }
#pragma unroll
            for (int ky = 0; ky < KS; ky++) {
                const int kk = cil * KK + ky * KS + kx;
                const float* wrow = &ws[kk][cg * 16];
                ulonglong2 w0 = *reinterpret_cast<const ulonglong2*>(wrow);
                ulonglong2 w1 = *reinterpret_cast<const ulonglong2*>(wrow + 4);
                ulonglong2 w2 = *reinterpret_cast<const ulonglong2*>(wrow + 8);
                ulonglong2 w3 = *reinterpret_cast<const ulonglong2*>(wrow + 12);
#pragma unroll
                for (int p = 0; p < 2; p++) {
                    unsigned long long xc2 = x2[ky + p], cv2 = c2[ky + p];
                    ffma2(accN[p][0], w0.x, xc2); ffma2(accD[p][0], w0.x, cv2);
                    ffma2(accN[p][1], w0.y, xc2); ffma2(accD[p][1], w0.y, cv2);
                    ffma2(accN[p][2], w1.x, xc2); ffma2(accD[p][2], w1.x, cv2);
                    ffma2(accN[p][3], w1.y, xc2); ffma2(accD[p][3], w1.y, cv2);
                    ffma2(accN[p][4], w2.x, xc2); ffma2(accD[p][4], w2.x, cv2);
                    ffma2(accN[p][5], w2.y, xc2); ffma2(accD[p][5], w2.y, cv2);
                    ffma2(accN[p][6], w3.x, xc2); ffma2(accD[p][6], w3.x, cv2);
                    ffma2(accN[p][7], w3.y, xc2); ffma2(accD[p][7], w3.y, cv2);
                }
            }
        }
    }

    constexpr long PLANE = (long)HH * WW;
    const int xg = bx + tx;
#pragma unroll
    for (int p = 0; p < 2; p++) {
        const int yg = by + ry + p;
        const long pix = (long)yg * WW + xg;
#pragma unroll
        for (int q = 0; q < 8; q++) {
            float n0, n1, d0, d1;
            unpack2(accN[p][q], n0, n1);
            unpack2(accD[p][q], d0, d1);
            const int co0 = cg * 16 + 2 * q;
            const long o0 = ((long)b * 32 + co0) * PLANE + pix;
            xout[o0]         = n0 / (d0 + EPSF) + bias[co0];
            xout[o0 + PLANE] = n1 / (d1 + EPSF) + bias[co0 + 1];
            cout[o0]         = d0 * winv[co0];
            cout[o0 + PLANE] = d1 * winv[co0 + 1];
        }
    }
}

// ---------------------------------------------------------------------------
// 2x2 stride-2 confidence-argmax pool (first-occurrence argmax like jnp).
// ---------------------------------------------------------------------------
__global__ void pool_kernel(const float* __restrict__ xin, const float* __restrict__ cin,
                            float* __restrict__ xout, float* __restrict__ cout,
                            int Ho, int Wo) {
    long i = (long)blockIdx.x * blockDim.x + threadIdx.x;
    long total = 64L * Ho * Wo;
    if (i >= total) return;
    int xo = (int)(i % Wo);
    long t = i / Wo;
    int yo = (int)(t % Ho);
    long bc = t / Ho;
    const int Wi = 2 * Wo;
    long ib = bc * 4L * Ho * Wo + (long)(2 * yo) * Wi + 2 * xo;
    float c00 = cin[ib], c01 = cin[ib + 1], c10 = cin[ib + Wi], c11 = cin[ib + Wi + 1];
    float best = c00; int bi = 0;
    if (c01 > best) { best = c01; bi = 1; }
    if (c10 > best) { best = c10; bi = 2; }
    if (c11 > best) { best = c11; bi = 3; }
    long off = (long)(bi >> 1) * Wi + (bi & 1);
    xout[i] = xin[ib + off];
    cout[i] = best * 0.25f;
}

// ---------------------------------------------------------------------------
// Final 1x1 nconv (32 -> 1)
// ---------------------------------------------------------------------------
__global__ void final1x1_kernel(const float* __restrict__ xin, const float* __restrict__ cin,
                                const float* __restrict__ w7, const float* __restrict__ b7,
                                float* __restrict__ out) {
    constexpr long HW = 512L * 512L;
    long i = (long)blockIdx.x * blockDim.x + threadIdx.x;
    if (i >= 2 * HW) return;
    int b = (int)(i / HW);
    long p = i - (long)b * HW;
    const float* xb = xin + (long)b * 32 * HW + p;
    const float* cb = cin + (long)b * 32 * HW + p;
    float n = 0.f, d = 0.f;
#pragma unroll
    for (int ci = 0; ci < 32; ci++) {
        float wv = __ldg(w7 + ci);
        float cv = __ldg(cb + (long)ci * HW);
        float xv = __ldg(xb + (long)ci * HW);
        n += wv * xv * cv;
        d += wv * cv;
    }
    out[i] = n / (d + EPSF) + __ldg(b7);
}

// ---------------------------------------------------------------------------
// Launch sequence
// ---------------------------------------------------------------------------
extern "C" void kernel_launch(void* const* d_in, const int* in_sizes, int n_in,
                              void* d_out, int out_size) {
    const float* x  = (const float*)d_in[0];
    const float* w1 = (const float*)d_in[1];  const float* b1 = (const float*)d_in[2];
    const float* w2 = (const float*)d_in[3];  const float* b2 = (const float*)d_in[4];
    const float* w3 = (const float*)d_in[5];  const float* b3 = (const float*)d_in[6];
    const float* w4 = (const float*)d_in[7];  const float* b4 = (const float*)d_in[8];
    const float* w5 = (const float*)d_in[9];  const float* b5 = (const float*)d_in[10];
    const float* w6 = (const float*)d_in[11]; const float* b6 = (const float*)d_in[12];
    const float* w7 = (const float*)d_in[13]; const float* b7 = (const float*)d_in[14];

    float* pool = nullptr;
    cudaGetSymbolAddress((void**)&pool, g_pool);

    float* P0x = pool;
    float* P0c = pool + N512;
    float* P1x = pool + 2 * N512;
    float* P1c = pool + 3 * N512;
    float* X1  = pool + 4 * N512;
    float* C1  = pool + 5 * N512;
    float* X2  = pool + 6 * N512;
    float* C2  = X2 + N256;
    float* X3  = C2 + N256;
    float* C3  = X3 + N128;
    float* S0x = C3 + N128;
    float* S0c = S0x + N256;
    float* S1x = S0c + N256;
    float* S1c = S1x + N256;
    float* WS  = S1c + N256;

    const long HW = 512L * 512;

    wsum_kernel<<<7, 32>>>(w1, w2, w3, w4, w5, w6, w7, WS);

    // Encoder full-res: L1 (1->32), L2, L3 @512
    nconv_fast<1, 5, 512, 512, 1><<<dim3(16, 64, 2), 256>>>(
        x, x + HW, 2 * HW, HW, w1, b1, WS + 0, P0x, P0c);
    nconv_fast<32, 5, 512, 512, 8><<<dim3(16, 64, 2), 256>>>(
        P0x, P0c, 32 * HW, HW, w2, b2, WS + 32, P1x, P1c);
    nconv_fast<32, 5, 512, 512, 8><<<dim3(16, 64, 2), 256>>>(
        P1x, P1c, 32 * HW, HW, w3, b3, WS + 64, X1, C1);

    // Down 1: pool 512->256, L2, L3 @256
    pool_kernel<<<(int)((64L * 256 * 256 + 255) / 256), 256>>>(X1, C1, S0x, S0c, 256, 256);
    nconv_fast<32, 5, 256, 256, 8><<<dim3(8, 32, 2), 256>>>(
        S0x, S0c, 32L * 256 * 256, 256L * 256, w2, b2, WS + 32, S1x, S1c);
    nconv_fast<32, 5, 256, 256, 8><<<dim3(8, 32, 2), 256>>>(
        S1x, S1c, 32L * 256 * 256, 256L * 256, w3, b3, WS + 64, X2, C2);

    // Down 2: pool 256->128, L2 @128
    pool_kernel<<<(int)((64L * 128 * 128 + 255) / 256), 256>>>(X2, C2, S0x, S0c, 128, 128);
    nconv_fast<32, 5, 128, 128, 8><<<dim3(4, 16, 2), 256>>>(
        S0x, S0c, 32L * 128 * 128, 128L * 128, w2, b2, WS + 32, X3, C3);

    // Down 3: pool 128->64, L2 @64
    pool_kernel<<<(int)((64L * 64 * 64 + 255) / 256), 256>>>(X3, C3, S1x, S1c, 64, 64);
    nconv_fast<32, 5, 64, 64, 8><<<dim3(2, 8, 2), 256>>>(
        S1x, S1c, 32L * 64 * 64, 64L * 64, w2, b2, WS + 32, S0x, S0c);

    // Decoder
    nconv_cat_fast<128, 128><<<dim3(4, 16, 2), 256>>>(
        X3, C3, 0, S0x, S0c, 1, w4, b4, WS + 96, S1x, S1c);
    nconv_cat_fast<256, 256><<<dim3(8, 32, 2), 256>>>(
        X2, C2, 0, S1x, S1c, 1, w5, b5, WS + 128, S0x, S0c);
    nconv_cat_fast<512, 512><<<dim3(16, 64, 2), 256>>>(
        S0x, S0c, 1, X1, C1, 0, w6, b6, WS + 160, P0x, P0c);

    final1x1_kernel<<<2048, 256>>>(P0x, P0c, w7, b7, (float*)d_out);
}

// round 4
// speedup vs baseline: 1.3212x; 1.0007x over previous
#include <cuda_runtime.h>

#define EPSF 1e-20f

// ---------------------------------------------------------------------------
// Scratch pool (static __device__ memory — no allocations allowed).
// ---------------------------------------------------------------------------
static constexpr long N512 = 2L * 32 * 512 * 512;
static constexpr long N256 = 2L * 32 * 256 * 256;
static constexpr long N128 = 2L * 32 * 128 * 128;
static constexpr long POOL_FLOATS = 6 * N512 + 2 * N256 + 2 * N128 + 4 * N256 + 256;

__device__ float g_pool[POOL_FLOATS];

// ---------------------------------------------------------------------------
// Packed f32x2 helpers
// ---------------------------------------------------------------------------
__device__ __forceinline__ unsigned long long pack2(float a, float b) {
    unsigned long long r;
    asm("mov.b64 %0, {%1, %2};" : "=l"(r) : "f"(a), "f"(b));
    return r;
}
__device__ __forceinline__ void unpack2(unsigned long long v, float& a, float& b) {
    asm("mov.b64 {%0, %1}, %2;" : "=f"(a), "=f"(b) : "l"(v));
}
__device__ __forceinline__ void ffma2(unsigned long long& acc, unsigned long long w2,
                                      unsigned long long m2) {
    asm("fma.rn.f32x2 %0, %1, %2, %0;" : "+l"(acc) : "l"(w2), "l"(m2));
}

// ---------------------------------------------------------------------------
// cp.async helpers (LDGSTS)
// ---------------------------------------------------------------------------
__device__ __forceinline__ void cp_async4(unsigned dst, const float* src, bool valid) {
    int sz = valid ? 4 : 0;
    asm volatile("cp.async.ca.shared.global [%0], [%1], 4, %2;\n"
                 :: "r"(dst), "l"(src), "r"(sz));
}
__device__ __forceinline__ void cp_commit() {
    asm volatile("cp.async.commit_group;\n");
}
template <int N>
__device__ __forceinline__ void cp_wait() {
    asm volatile("cp.async.wait_group %0;\n" :: "n"(N));
}

// ---------------------------------------------------------------------------
// Per-layer 1/sum(w): inv[l*32+co] = 1 / sum(w_l[co,:,:,:])
// ---------------------------------------------------------------------------
__global__ void wsum_kernel(const float* __restrict__ w1, const float* __restrict__ w2,
                            const float* __restrict__ w3, const float* __restrict__ w4,
                            const float* __restrict__ w5, const float* __restrict__ w6,
                            const float* __restrict__ w7, float* __restrict__ inv) {
    int l = blockIdx.x, co = threadIdx.x;
    const float* w; int n; int nco = 32;
    if      (l == 0) { w = w1; n = 1 * 25; }
    else if (l == 1) { w = w2; n = 32 * 25; }
    else if (l == 2) { w = w3; n = 32 * 25; }
    else if (l == 3) { w = w4; n = 64 * 9; }
    else if (l == 4) { w = w5; n = 64 * 9; }
    else if (l == 5) { w = w6; n = 64 * 9; }
    else             { w = w7; n = 32;  nco = 1; }
    if (co >= nco) return;
    float s = 0.f;
    for (int i = 0; i < n; i++) s += w[co * n + i];
    inv[l * 32 + co] = 1.0f / s;
}

// ---------------------------------------------------------------------------
// Fast normalized conv: KSxKS, CIN -> 32, same-padding.
// Block = 256 threads: 128 pixel-slots (32w x 4 slot-rows, 2 vertical pixels
// per slot) x 2 co-groups of 16. Raw x,c tiles double-buffered via cp.async;
// weights chunk-staged via cp.async; one barrier per input channel.
// ---------------------------------------------------------------------------
template <int CIN, int KS, int HH, int WW, int CHUNK>
__global__ __launch_bounds__(256)
void nconv_fast(const float* __restrict__ xin, const float* __restrict__ cin,
                long bstride, long cstride,
                const float* __restrict__ w, const float* __restrict__ bias,
                const float* __restrict__ winv,
                float* __restrict__ xout, float* __restrict__ cout) {
    constexpr int PAD = KS / 2, KK = KS * KS;
    constexpr int TW = 32, TH = 8;
    constexpr int SW = TW + KS - 1, SH = TH + KS - 1, NS = SH * SW;
    constexpr int NROW = KS + 1;
    __shared__ __align__(16) float ws[CHUNK * KK][32];
    __shared__ __align__(16) float cbuf[2][NS];
    __shared__ __align__(16) float xbuf[2][NS];

    const int tid = threadIdx.x;
    const int cg = tid >> 7;
    const int t = tid & 127;
    const int tx = t & 31;
    const int ry = (t >> 5) * 2;
    const int bx = blockIdx.x * TW, by = blockIdx.y * TH;
    const int b = blockIdx.z;

    unsigned long long accN[2][8], accD[2][8];
#pragma unroll
    for (int p = 0; p < 2; p++)
#pragma unroll
        for (int q = 0; q < 8; q++) { accN[p][q] = 0ULL; accD[p][q] = 0ULL; }

    const int sbase = ry * SW + tx;

    // Per-thread staging elements (<= 2 each; NS <= 512)
    const int i0 = tid, i1 = tid + 256;
    long g0 = 0, g1 = 0; bool v0 = false, v1 = false;
    {
        int r = i0 / SW, c = i0 - r * SW;
        int gy = by + r - PAD, gx = bx + c - PAD;
        v0 = (unsigned)gy < (unsigned)HH && (unsigned)gx < (unsigned)WW;
        g0 = v0 ? (long)gy * WW + gx : 0;
        if (i1 < NS) {
            r = i1 / SW; c = i1 - r * SW;
            gy = by + r - PAD; gx = bx + c - PAD;
            v1 = (unsigned)gy < (unsigned)HH && (unsigned)gx < (unsigned)WW;
            g1 = v1 ? (long)gy * WW + gx : 0;
        }
    }

    const unsigned ws_s = (unsigned)__cvta_generic_to_shared(&ws[0][0]);
    unsigned c_s[2], x_s[2];
    c_s[0] = (unsigned)__cvta_generic_to_shared(&cbuf[0][0]);
    c_s[1] = (unsigned)__cvta_generic_to_shared(&cbuf[1][0]);
    x_s[0] = (unsigned)__cvta_generic_to_shared(&xbuf[0][0]);
    x_s[1] = (unsigned)__cvta_generic_to_shared(&xbuf[1][0]);

    const float* xb = xin + (long)b * bstride;
    const float* cb = cin + (long)b * bstride;

    // Prefetch ci = 0
    {
        cp_async4(c_s[0] + i0 * 4, cb + g0, v0);
        cp_async4(x_s[0] + i0 * 4, xb + g0, v0);
        if (i1 < NS) {
            cp_async4(c_s[0] + i1 * 4, cb + g1, v1);
            cp_async4(x_s[0] + i1 * 4, xb + g1, v1);
        }
        cp_commit();
    }

#pragma unroll 1
    for (int ci = 0; ci < CIN; ci++) {
        const int bufc = ci & 1;
        const int cil = ci & (CHUNK - 1);
        cp_wait<0>();
        __syncthreads();

        if (cil == 0) {  // stage this chunk's weights (async)
            for (int i = tid; i < CHUNK * KK * 32; i += 256)
                cp_async4(ws_s + i * 4u,
                          w + ((long)(i & 31) * CIN + ci) * KK + (i >> 5), true);
            cp_commit();
        }
        if (ci + 1 < CIN) {  // prefetch next input channel
            const float* cp = cb + (long)(ci + 1) * cstride;
            const float* xp = xb + (long)(ci + 1) * cstride;
            const int nb = bufc ^ 1;
            cp_async4(c_s[nb] + i0 * 4, cp + g0, v0);
            cp_async4(x_s[nb] + i0 * 4, xp + g0, v0);
            if (i1 < NS) {
                cp_async4(c_s[nb] + i1 * 4, cp + g1, v1);
                cp_async4(x_s[nb] + i1 * 4, xp + g1, v1);
            }
            cp_commit();
        }
        if (cil == 0) {  // weights must land before compute
            if (ci + 1 < CIN) cp_wait<1>(); else cp_wait<0>();
            __syncthreads();
        }

        const float* csb = cbuf[bufc];
        const float* xsb = xbuf[bufc];
#pragma unroll
        for (int kx = 0; kx < KS; kx++) {
            unsigned long long c2[NROW], x2[NROW];
#pragma unroll
            for (int r = 0; r < NROW; r++) {
                float cv = csb[sbase + r * SW + kx];
                float xv = xsb[sbase + r * SW + kx];
                float xc = xv * cv;
                c2[r] = pack2(cv, cv);
                x2[r] = pack2(xc, xc);
            }
#pragma unroll
            for (int ky = 0; ky < KS; ky++) {
                const int kk = cil * KK + ky * KS + kx;
                const float* wrow = &ws[kk][cg * 16];
                ulonglong2 w0 = *reinterpret_cast<const ulonglong2*>(wrow);
                ulonglong2 w1 = *reinterpret_cast<const ulonglong2*>(wrow + 4);
                ulonglong2 w2 = *reinterpret_cast<const ulonglong2*>(wrow + 8);
                ulonglong2 w3 = *reinterpret_cast<const ulonglong2*>(wrow + 12);
#pragma unroll
                for (int p = 0; p < 2; p++) {
                    unsigned long long xc2 = x2[ky + p], cv2 = c2[ky + p];
                    ffma2(accN[p][0], w0.x, xc2); ffma2(accD[p][0], w0.x, cv2);
                    ffma2(accN[p][1], w0.y, xc2); ffma2(accD[p][1], w0.y, cv2);
                    ffma2(accN[p][2], w1.x, xc2); ffma2(accD[p][2], w1.x, cv2);
                    ffma2(accN[p][3], w1.y, xc2); ffma2(accD[p][3], w1.y, cv2);
                    ffma2(accN[p][4], w2.x, xc2); ffma2(accD[p][4], w2.x, cv2);
                    ffma2(accN[p][5], w2.y, xc2); ffma2(accD[p][5], w2.y, cv2);
                    ffma2(accN[p][6], w3.x, xc2); ffma2(accD[p][6], w3.x, cv2);
                    ffma2(accN[p][7], w3.y, xc2); ffma2(accD[p][7], w3.y, cv2);
                }
            }
        }
    }

    constexpr long PLANE = (long)HH * WW;
    const int xg = bx + tx;
#pragma unroll
    for (int p = 0; p < 2; p++) {
        const int yg = by + ry + p;
        const long pix = (long)yg * WW + xg;
#pragma unroll
        for (int q = 0; q < 8; q++) {
            float n0, n1, d0, d1;
            unpack2(accN[p][q], n0, n1);
            unpack2(accD[p][q], d0, d1);
            const int co0 = cg * 16 + 2 * q;
            const long o0 = ((long)b * 32 + co0) * PLANE + pix;
            xout[o0]         = n0 / (d0 + EPSF) + bias[co0];
            xout[o0 + PLANE] = n1 / (d1 + EPSF) + bias[co0 + 1];
            cout[o0]         = d0 * winv[co0];
            cout[o0 + PLANE] = d1 * winv[co0 + 1];
        }
    }
}

// ---------------------------------------------------------------------------
// Decoder fast nconv: 3x3, CIN=64 -> 32, fused concat + nearest-2x upsample,
// same cp.async double-buffered pipeline. Group flagged "half" reads half-res.
// ---------------------------------------------------------------------------
template <int HH, int WW>
__global__ __launch_bounds__(256)
void nconv_cat_fast(const float* __restrict__ x0p, const float* __restrict__ c0p, int half0,
                    const float* __restrict__ x1p, const float* __restrict__ c1p, int half1,
                    const float* __restrict__ w, const float* __restrict__ bias,
                    const float* __restrict__ winv,
                    float* __restrict__ xout, float* __restrict__ cout) {
    constexpr int KS = 3, PAD = 1, KK = 9, CIN = 64, CHUNK = 16;
    constexpr int TW = 32, TH = 8;
    constexpr int SW = TW + KS - 1, SH = TH + KS - 1, NS = SH * SW;
    constexpr int NROW = KS + 1;
    constexpr int W2 = WW / 2;
    __shared__ __align__(16) float ws[CHUNK * KK][32];
    __shared__ __align__(16) float cbuf[2][NS];
    __shared__ __align__(16) float xbuf[2][NS];

    const int tid = threadIdx.x;
    const int cg = tid >> 7;
    const int t = tid & 127;
    const int tx = t & 31;
    const int ry = (t >> 5) * 2;
    const int bx = blockIdx.x * TW, by = blockIdx.y * TH;
    const int b = blockIdx.z;

    unsigned long long accN[2][8], accD[2][8];
#pragma unroll
    for (int p = 0; p < 2; p++)
#pragma unroll
        for (int q = 0; q < 8; q++) { accN[p][q] = 0ULL; accD[p][q] = 0ULL; }

    const int sbase = ry * SW + tx;

    // Per-thread staging elements: full-res and half-res gather offsets
    const int i0 = tid, i1 = tid + 256;
    long g0F = 0, g0H = 0, g1F = 0, g1H = 0; bool v0 = false, v1 = false;
    if (i0 < NS) {
        int r = i0 / SW, c = i0 - r * SW;
        int gy = by + r - PAD, gx = bx + c - PAD;
        v0 = (unsigned)gy < (unsigned)HH && (unsigned)gx < (unsigned)WW;
        g0F = v0 ? (long)gy * WW + gx : 0;
        g0H = v0 ? (long)(gy >> 1) * W2 + (gx >> 1) : 0;
    }
    if (i1 < NS) {
        int r = i1 / SW, c = i1 - r * SW;
        int gy = by + r - PAD, gx = bx + c - PAD;
        v1 = (unsigned)gy < (unsigned)HH && (unsigned)gx < (unsigned)WW;
        g1F = v1 ? (long)gy * WW + gx : 0;
        g1H = v1 ? (long)(gy >> 1) * W2 + (gx >> 1) : 0;
    }

    const unsigned ws_s = (unsigned)__cvta_generic_to_shared(&ws[0][0]);
    unsigned c_s[2], x_s[2];
    c_s[0] = (unsigned)__cvta_generic_to_shared(&cbuf[0][0]);
    c_s[1] = (unsigned)__cvta_generic_to_shared(&cbuf[1][0]);
    x_s[0] = (unsigned)__cvta_generic_to_shared(&xbuf[0][0]);
    x_s[1] = (unsigned)__cvta_generic_to_shared(&xbuf[1][0]);

    // prefetch helper (inlined): channel ci into buffer nb
    auto prefetch = [&](int ci, int nb) {
        const int grp = ci >> 5;
        const float* xs = grp ? x1p : x0p;
        const float* cc = grp ? c1p : c0p;
        const int half = grp ? half1 : half0;
        const long plane = half ? (long)(HH / 2) * W2 : (long)HH * WW;
        const float* xp = xs + ((long)b * 32 + (ci & 31)) * plane;
        const float* cp = cc + ((long)b * 32 + (ci & 31)) * plane;
        const long o0 = half ? g0H : g0F;
        const long o1 = half ? g1H : g1F;
        if (i0 < NS) {
            cp_async4(c_s[nb] + i0 * 4, cp + o0, v0);
            cp_async4(x_s[nb] + i0 * 4, xp + o0, v0);
        }
        if (i1 < NS) {
            cp_async4(c_s[nb] + i1 * 4, cp + o1, v1);
            cp_async4(x_s[nb] + i1 * 4, xp + o1, v1);
        }
        cp_commit();
    };

    prefetch(0, 0);

#pragma unroll 1
    for (int ci = 0; ci < CIN; ci++) {
        const int bufc = ci & 1;
        const int cil = ci & (CHUNK - 1);
        cp_wait<0>();
        __syncthreads();

        if (cil == 0) {
            for (int i = tid; i < CHUNK * KK * 32; i += 256)
                cp_async4(ws_s + i * 4u,
                          w + ((long)(i & 31) * CIN + ci) * KK + (i >> 5), true);
            cp_commit();
        }
        if (ci + 1 < CIN) prefetch(ci + 1, bufc ^ 1);
        if (cil == 0) {
            if (ci + 1 < CIN) cp_wait<1>(); else cp_wait<0>();
            __syncthreads();
        }

        const float* csb = cbuf[bufc];
        const float* xsb = xbuf[bufc];
#pragma unroll
        for (int kx = 0; kx < KS; kx++) {
            unsigned long long c2[NROW], x2[NROW];
#pragma unroll
            for (int r = 0; r < NROW; r++) {
                float cv = csb[sbase + r * SW + kx];
                float xv = xsb[sbase + r * SW + kx];
                float xc = xv * cv;
                c2[r] = pack2(cv, cv);
                x2[r] = pack2(xc, xc);
            }
#pragma unroll
            for (int ky = 0; ky < KS; ky++) {
                const int kk = cil * KK + ky * KS + kx;
                const float* wrow = &ws[kk][cg * 16];
                ulonglong2 w0 = *reinterpret_cast<const ulonglong2*>(wrow);
                ulonglong2 w1 = *reinterpret_cast<const ulonglong2*>(wrow + 4);
                ulonglong2 w2 = *reinterpret_cast<const ulonglong2*>(wrow + 8);
                ulonglong2 w3 = *reinterpret_cast<const ulonglong2*>(wrow + 12);
#pragma unroll
                for (int p = 0; p < 2; p++) {
                    unsigned long long xc2 = x2[ky + p], cv2 = c2[ky + p];
                    ffma2(accN[p][0], w0.x, xc2); ffma2(accD[p][0], w0.x, cv2);
                    ffma2(accN[p][1], w0.y, xc2); ffma2(accD[p][1], w0.y, cv2);
                    ffma2(accN[p][2], w1.x, xc2); ffma2(accD[p][2], w1.x, cv2);
                    ffma2(accN[p][3], w1.y, xc2); ffma2(accD[p][3], w1.y, cv2);
                    ffma2(accN[p][4], w2.x, xc2); ffma2(accD[p][4], w2.x, cv2);
                    ffma2(accN[p][5], w2.y, xc2); ffma2(accD[p][5], w2.y, cv2);
                    ffma2(accN[p][6], w3.x, xc2); ffma2(accD[p][6], w3.x, cv2);
                    ffma2(accN[p][7], w3.y, xc2); ffma2(accD[p][7], w3.y, cv2);
                }
            }
        }
    }

    constexpr long PLANE = (long)HH * WW;
    const int xg = bx + tx;
#pragma unroll
    for (int p = 0; p < 2; p++) {
        const int yg = by + ry + p;
        const long pix = (long)yg * WW + xg;
#pragma unroll
        for (int q = 0; q < 8; q++) {
            float n0, n1, d0, d1;
            unpack2(accN[p][q], n0, n1);
            unpack2(accD[p][q], d0, d1);
            const int co0 = cg * 16 + 2 * q;
            const long o0 = ((long)b * 32 + co0) * PLANE + pix;
            xout[o0]         = n0 / (d0 + EPSF) + bias[co0];
            xout[o0 + PLANE] = n1 / (d1 + EPSF) + bias[co0 + 1];
            cout[o0]         = d0 * winv[co0];
            cout[o0 + PLANE] = d1 * winv[co0 + 1];
        }
    }
}

// ---------------------------------------------------------------------------
// 2x2 stride-2 confidence-argmax pool (first-occurrence argmax like jnp).
// ---------------------------------------------------------------------------
__global__ void pool_kernel(const float* __restrict__ xin, const float* __restrict__ cin,
                            float* __restrict__ xout, float* __restrict__ cout,
                            int Ho, int Wo) {
    long i = (long)blockIdx.x * blockDim.x + threadIdx.x;
    long total = 64L * Ho * Wo;
    if (i >= total) return;
    int xo = (int)(i % Wo);
    long t = i / Wo;
    int yo = (int)(t % Ho);
    long bc = t / Ho;
    const int Wi = 2 * Wo;
    long ib = bc * 4L * Ho * Wo + (long)(2 * yo) * Wi + 2 * xo;
    float c00 = cin[ib], c01 = cin[ib + 1], c10 = cin[ib + Wi], c11 = cin[ib + Wi + 1];
    float best = c00; int bi = 0;
    if (c01 > best) { best = c01; bi = 1; }
    if (c10 > best) { best = c10; bi = 2; }
    if (c11 > best) { best = c11; bi = 3; }
    long off = (long)(bi >> 1) * Wi + (bi & 1);
    xout[i] = xin[ib + off];
    cout[i] = best * 0.25f;
}

// ---------------------------------------------------------------------------
// Final 1x1 nconv (32 -> 1)
// ---------------------------------------------------------------------------
__global__ void final1x1_kernel(const float* __restrict__ xin, const float* __restrict__ cin,
                                const float* __restrict__ w7, const float* __restrict__ b7,
                                float* __restrict__ out) {
    constexpr long HW = 512L * 512L;
    long i = (long)blockIdx.x * blockDim.x + threadIdx.x;
    if (i >= 2 * HW) return;
    int b = (int)(i / HW);
    long p = i - (long)b * HW;
    const float* xb = xin + (long)b * 32 * HW + p;
    const float* cb = cin + (long)b * 32 * HW + p;
    float n = 0.f, d = 0.f;
#pragma unroll
    for (int ci = 0; ci < 32; ci++) {
        float wv = __ldg(w7 + ci);
        float cv = __ldg(cb + (long)ci * HW);
        float xv = __ldg(xb + (long)ci * HW);
        n += wv * xv * cv;
        d += wv * cv;
    }
    out[i] = n / (d + EPSF) + __ldg(b7);
}

// ---------------------------------------------------------------------------
// Launch sequence
// ---------------------------------------------------------------------------
extern "C" void kernel_launch(void* const* d_in, const int* in_sizes, int n_in,
                              void* d_out, int out_size) {
    const float* x  = (const float*)d_in[0];
    const float* w1 = (const float*)d_in[1];  const float* b1 = (const float*)d_in[2];
    const float* w2 = (const float*)d_in[3];  const float* b2 = (const float*)d_in[4];
    const float* w3 = (const float*)d_in[5];  const float* b3 = (const float*)d_in[6];
    const float* w4 = (const float*)d_in[7];  const float* b4 = (const float*)d_in[8];
    const float* w5 = (const float*)d_in[9];  const float* b5 = (const float*)d_in[10];
    const float* w6 = (const float*)d_in[11]; const float* b6 = (const float*)d_in[12];
    const float* w7 = (const float*)d_in[13]; const float* b7 = (const float*)d_in[14];

    float* pool = nullptr;
    cudaGetSymbolAddress((void**)&pool, g_pool);

    float* P0x = pool;
    float* P0c = pool + N512;
    float* P1x = pool + 2 * N512;
    float* P1c = pool + 3 * N512;
    float* X1  = pool + 4 * N512;
    float* C1  = pool + 5 * N512;
    float* X2  = pool + 6 * N512;
    float* C2  = X2 + N256;
    float* X3  = C2 + N256;
    float* C3  = X3 + N128;
    float* S0x = C3 + N128;
    float* S0c = S0x + N256;
    float* S1x = S0c + N256;
    float* S1c = S1x + N256;
    float* WS  = S1c + N256;

    const long HW = 512L * 512;

    wsum_kernel<<<7, 32>>>(w1, w2, w3, w4, w5, w6, w7, WS);

    // Encoder full-res: L1 (1->32), L2, L3 @512
    nconv_fast<1, 5, 512, 512, 1><<<dim3(16, 64, 2), 256>>>(
        x, x + HW, 2 * HW, HW, w1, b1, WS + 0, P0x, P0c);
    nconv_fast<32, 5, 512, 512, 8><<<dim3(16, 64, 2), 256>>>(
        P0x, P0c, 32 * HW, HW, w2, b2, WS + 32, P1x, P1c);
    nconv_fast<32, 5, 512, 512, 8><<<dim3(16, 64, 2), 256>>>(
        P1x, P1c, 32 * HW, HW, w3, b3, WS + 64, X1, C1);

    // Down 1: pool 512->256, L2, L3 @256
    pool_kernel<<<(int)((64L * 256 * 256 + 255) / 256), 256>>>(X1, C1, S0x, S0c, 256, 256);
    nconv_fast<32, 5, 256, 256, 8><<<dim3(8, 32, 2), 256>>>(
        S0x, S0c, 32L * 256 * 256, 256L * 256, w2, b2, WS + 32, S1x, S1c);
    nconv_fast<32, 5, 256, 256, 8><<<dim3(8, 32, 2), 256>>>(
        S1x, S1c, 32L * 256 * 256, 256L * 256, w3, b3, WS + 64, X2, C2);

    // Down 2: pool 256->128, L2 @128
    pool_kernel<<<(int)((64L * 128 * 128 + 255) / 256), 256>>>(X2, C2, S0x, S0c, 128, 128);
    nconv_fast<32, 5, 128, 128, 8><<<dim3(4, 16, 2), 256>>>(
        S0x, S0c, 32L * 128 * 128, 128L * 128, w2, b2, WS + 32, X3, C3);

    // Down 3: pool 128->64, L2 @64
    pool_kernel<<<(int)((64L * 64 * 64 + 255) / 256), 256>>>(X3, C3, S1x, S1c, 64, 64);
    nconv_fast<32, 5, 64, 64, 8><<<dim3(2, 8, 2), 256>>>(
        S1x, S1c, 32L * 64 * 64, 64L * 64, w2, b2, WS + 32, S0x, S0c);

    // Decoder
    nconv_cat_fast<128, 128><<<dim3(4, 16, 2), 256>>>(
        X3, C3, 0, S0x, S0c, 1, w4, b4, WS + 96, S1x, S1c);
    nconv_cat_fast<256, 256><<<dim3(8, 32, 2), 256>>>(
        X2, C2, 0, S1x, S1c, 1, w5, b5, WS + 128, S0x, S0c);
    nconv_cat_fast<512, 512><<<dim3(16, 64, 2), 256>>>(
        S0x, S0c, 1, X1, C1, 0, w6, b6, WS + 160, P0x, P0c);

    final1x1_kernel<<<2048, 256>>>(P0x, P0c, w7, b7, (float*)d_out);
}